// round 1
// baseline (speedup 1.0000x reference)
#include <cuda_runtime.h>
#include <math.h>

#define N_NODES 20000
#define N_EDGES 320000
#define N_ITEMS (N_EDGES + N_NODES)

// ---------------- scratch (device globals; no allocs allowed) ----------------
__device__ float g_xl[N_NODES * 256];
__device__ float g_xr[N_NODES * 256];
__device__ float g_ex[N_ITEMS * 2];
__device__ float g_den[N_NODES * 2];
__device__ float g_agg[N_NODES * 256];
__device__ float g_zv1[N_NODES * 128];
__device__ float g_zv2[N_NODES * 128];
__device__ float g_gi[N_NODES * 384];
__device__ float g_h[N_NODES * 128];
__device__ float g_Wt[128 * 384];
__device__ float g_easum[16];
__device__ float g_eeloop1[256];
__device__ float g_eeloop2[128];

// ---------------- utility kernels ----------------
__global__ void zero_kernel(float* p, int n) {
    int i = blockIdx.x * blockDim.x + threadIdx.x;
    if (i < n) p[i] = 0.f;
}

// column sums of edge_attr [E,16] -> easum[16]
__global__ void ea_colsum(const float* __restrict__ ea, float* easum, int E) {
    int tid = threadIdx.x;
    int k = tid & 15;
    int slot = (blockIdx.x * blockDim.x + tid) >> 4;
    int nslots = (gridDim.x * blockDim.x) >> 4;
    float s = 0.f;
    for (int e = slot; e < E; e += nslots) s += ea[(size_t)e * 16 + k];
    s += __shfl_down_sync(0xffffffffu, s, 16);
    __shared__ float sh[16];
    if (tid < 16) sh[tid] = 0.f;
    __syncthreads();
    if ((tid & 31) < 16) atomicAdd(&sh[k], s);
    __syncthreads();
    if (tid < 16) atomicAdd(&easum[tid], sh[tid]);
}

// eeloop[col] = (easum/E) @ We  for self-loop edges (fill_value='mean')
__global__ void compute_eeloop(const float* __restrict__ easum,
                               const float* __restrict__ We,
                               float* __restrict__ eeloop, int M, float invE) {
    int col = blockIdx.x * blockDim.x + threadIdx.x;
    if (col >= M) return;
    float s = 0.f;
#pragma unroll
    for (int k = 0; k < 16; k++) s = fmaf(easum[k] * invE, We[k * M + col], s);
    eeloop[col] = s;
}

// transpose W_ih [384,128] -> Wt [128,384]
__global__ void transpose_wih(const float* __restrict__ W, float* __restrict__ Wt) {
    int i = blockIdx.x * blockDim.x + threadIdx.x;
    if (i < 384 * 128) {
        int j = i / 128, k = i % 128;
        Wt[k * 384 + j] = W[i];
    }
}

// ---------------- generic GEMM: C[n,M] = A[n,K] @ B[K,M] + bias ----------------
// requirements: K%16==0, M%64==0, 256 threads, 64x64 tile, 4x4 per thread
__global__ void gemm_bias(const float* __restrict__ A, const float* __restrict__ B,
                          const float* __restrict__ bias, float* __restrict__ C,
                          int n, int K, int M) {
    __shared__ float As[64][16];
    __shared__ float Bs[16][64];
    int tid = threadIdx.x;
    int tx = tid & 15, ty = tid >> 4;
    int row0 = blockIdx.y * 64;
    int col0 = blockIdx.x * 64;
    int la_row = tid >> 2;
    int la_col = (tid & 3) * 4;
    int lb_row = tid >> 4;
    int lb_col = (tid & 15) * 4;
    float acc[4][4] = {};
    for (int k0 = 0; k0 < K; k0 += 16) {
        float4 av = make_float4(0.f, 0.f, 0.f, 0.f);
        int ar = row0 + la_row;
        if (ar < n) av = *(const float4*)&A[(size_t)ar * K + k0 + la_col];
        *(float4*)&As[la_row][la_col] = av;
        float4 bv = *(const float4*)&B[(size_t)(k0 + lb_row) * M + col0 + lb_col];
        *(float4*)&Bs[lb_row][lb_col] = bv;
        __syncthreads();
#pragma unroll
        for (int kk = 0; kk < 16; kk++) {
            float a[4];
#pragma unroll
            for (int i = 0; i < 4; i++) a[i] = As[ty * 4 + i][kk];
            float4 b4 = *(float4*)&Bs[kk][tx * 4];
            float b[4] = {b4.x, b4.y, b4.z, b4.w};
#pragma unroll
            for (int i = 0; i < 4; i++)
#pragma unroll
                for (int j = 0; j < 4; j++) acc[i][j] = fmaf(a[i], b[j], acc[i][j]);
        }
        __syncthreads();
    }
#pragma unroll
    for (int i = 0; i < 4; i++) {
        int r = row0 + ty * 4 + i;
        if (r < n) {
#pragma unroll
            for (int j = 0; j < 4; j++) {
                int c = col0 + tx * 4 + j;
                C[(size_t)r * M + c] = acc[i][j] + bias[c];
            }
        }
    }
}

// ---------------- GATv2 edge score (exp of attention logits + denom) ----------------
template <int HEADS>
__global__ void edge_score(const int* __restrict__ src, const int* __restrict__ dst,
                           const float* __restrict__ ea,
                           const float* __restrict__ We, const float* __restrict__ att,
                           const float* __restrict__ eeloop,
                           const float* __restrict__ xl, const float* __restrict__ xr,
                           float* __restrict__ ex_out, float* __restrict__ den) {
    constexpr int M = HEADS * 128;
    __shared__ float sWe[16 * M];
    __shared__ float sAtt[M];
    __shared__ float sLoop[M];
    for (int i = threadIdx.x; i < 16 * M; i += blockDim.x) sWe[i] = We[i];
    for (int i = threadIdx.x; i < M; i += blockDim.x) {
        sAtt[i] = att[i];
        sLoop[i] = eeloop[i];
    }
    __syncthreads();
    int lane = threadIdx.x & 31;
    int warp = (blockIdx.x * blockDim.x + threadIdx.x) >> 5;
    int nw = (gridDim.x * blockDim.x) >> 5;
    for (int item = warp; item < N_ITEMS; item += nw) {
        int s, d;
        bool lp = item >= N_EDGES;
        if (lp) { s = item - N_EDGES; d = s; }
        else { s = src[item]; d = dst[item]; }
        float eak[16];
        if (!lp) {
            float eav = (lane < 16) ? ea[(size_t)item * 16 + lane] : 0.f;
#pragma unroll
            for (int k = 0; k < 16; k++) eak[k] = __shfl_sync(0xffffffffu, eav, k);
        }
        float acc[HEADS];
#pragma unroll
        for (int h = 0; h < HEADS; h++) acc[h] = 0.f;
#pragma unroll
        for (int t = 0; t < HEADS * 4; t++) {
            int col = lane + 32 * t;
            float ee;
            if (lp) ee = sLoop[col];
            else {
                ee = 0.f;
#pragma unroll
                for (int k = 0; k < 16; k++) ee = fmaf(eak[k], sWe[k * M + col], ee);
            }
            float msg = xl[(size_t)s * M + col] + xr[(size_t)d * M + col] + ee;
            float lr = msg > 0.f ? msg : 0.2f * msg;
            acc[t / 4] = fmaf(lr, sAtt[col], acc[t / 4]);
        }
#pragma unroll
        for (int h = 0; h < HEADS; h++) {
            float v = acc[h];
#pragma unroll
            for (int o = 16; o > 0; o >>= 1) v += __shfl_xor_sync(0xffffffffu, v, o);
            if (lane == 0) {
                float exv = expf(v);
                ex_out[(size_t)item * HEADS + h] = exv;
                atomicAdd(&den[d * HEADS + h], exv);
            }
        }
    }
}

// ---------------- GATv2 aggregation: agg[dst] += alpha * xl[src] ----------------
template <int HEADS>
__global__ void edge_aggregate(const int* __restrict__ src, const int* __restrict__ dst,
                               const float* __restrict__ ex, const float* __restrict__ den,
                               const float* __restrict__ xl, float* __restrict__ agg) {
    constexpr int M = HEADS * 128;
    int lane = threadIdx.x & 31;
    int warp = (blockIdx.x * blockDim.x + threadIdx.x) >> 5;
    int nw = (gridDim.x * blockDim.x) >> 5;
    for (int item = warp; item < N_ITEMS; item += nw) {
        int s, d;
        if (item >= N_EDGES) { s = item - N_EDGES; d = s; }
        else { s = src[item]; d = dst[item]; }
        float alpha[HEADS];
#pragma unroll
        for (int h = 0; h < HEADS; h++)
            alpha[h] = ex[(size_t)item * HEADS + h] / (den[d * HEADS + h] + 1e-16f);
#pragma unroll
        for (int t = 0; t < HEADS * 4; t++) {
            int col = lane + 32 * t;
            atomicAdd(&agg[(size_t)d * M + col], alpha[t / 4] * xl[(size_t)s * M + col]);
        }
    }
}

// ---------------- node finalize: mean heads + bias -> LN -> ELU ----------------
__global__ void node_finalize(const float* __restrict__ agg, const float* __restrict__ bias,
                              const float* __restrict__ gam, const float* __restrict__ bet,
                              float* __restrict__ out, int heads) {
    int gw = (blockIdx.x * blockDim.x + threadIdx.x) >> 5;
    int lane = threadIdx.x & 31;
    if (gw >= N_NODES) return;
    int M = heads * 128;
    float v[4];
#pragma unroll
    for (int q = 0; q < 4; q++) {
        int c = lane + 32 * q;
        float a = agg[(size_t)gw * M + c];
        if (heads == 2) a = 0.5f * (a + agg[(size_t)gw * M + 128 + c]);
        v[q] = a + bias[c];
    }
    float s = v[0] + v[1] + v[2] + v[3];
#pragma unroll
    for (int o = 16; o > 0; o >>= 1) s += __shfl_xor_sync(0xffffffffu, s, o);
    float mu = s * (1.f / 128.f);
    float vs = 0.f;
#pragma unroll
    for (int q = 0; q < 4; q++) {
        float dd = v[q] - mu;
        vs = fmaf(dd, dd, vs);
    }
#pragma unroll
    for (int o = 16; o > 0; o >>= 1) vs += __shfl_xor_sync(0xffffffffu, vs, o);
    float rstd = rsqrtf(vs * (1.f / 128.f) + 1e-5f);
#pragma unroll
    for (int q = 0; q < 4; q++) {
        int c = lane + 32 * q;
        float o = (v[q] - mu) * rstd * gam[c] + bet[c];
        out[(size_t)gw * 128 + c] = o > 0.f ? o : expm1f(o);
    }
}

// ---------------- GRU (h_prev = 0) ----------------
__global__ void gru_kernel(const float* __restrict__ gi, const float* __restrict__ bhh,
                           float* __restrict__ h) {
    int idx = blockIdx.x * blockDim.x + threadIdx.x;
    if (idx >= N_NODES * 128) return;
    int n = idx >> 7, c = idx & 127;
    const float* g = gi + (size_t)n * 384;
    float r = 1.f / (1.f + expf(-(g[c] + bhh[c])));
    float u = 1.f / (1.f + expf(-(g[128 + c] + bhh[128 + c])));
    float ng = tanhf(g[256 + c] + r * bhh[256 + c]);
    h[idx] = (1.f - u) * ng;
}

// ---------------- fused 3-layer edge classifier ----------------
// block = 128 threads, 32 edges per block.
// rep[e] = [h[src](128) | h[dst](128) | ea(16)]  (272)
__global__ void classifier(const float* __restrict__ h, const int* __restrict__ src,
                           const int* __restrict__ dst, const float* __restrict__ ea,
                           const float* __restrict__ Wc1, const float* __restrict__ bc1,
                           const float* __restrict__ Wc2, const float* __restrict__ bc2,
                           const float* __restrict__ Wc3, const float* __restrict__ bc3,
                           float* __restrict__ out, int E) {
    __shared__ float sm[32 * 272];  // reused: rep -> (o1 at [0..4095], o2 at [4096..6175])
    float* rep = sm;
    float* o1 = sm;
    float* o2 = sm + 32 * 128;
    const int tid = threadIdx.x;
    const int e0 = blockIdx.x * 32;

    // load rep tile
    for (int idx = tid; idx < 32 * 272; idx += 128) {
        int e = idx / 272, k = idx - e * 272;
        int ge = e0 + e;
        float v = 0.f;
        if (ge < E) {
            if (k < 128) v = h[(size_t)src[ge] * 128 + k];
            else if (k < 256) v = h[(size_t)dst[ge] * 128 + (k - 128)];
            else v = ea[(size_t)ge * 16 + (k - 256)];
        }
        rep[e * 272 + k] = v;
    }
    __syncthreads();

    // stage 1: o1[e][j] = relu(rep[e] . Wc1[:,j] + bc1[j]),  j = tid
    float acc[32];
    {
        float b1 = bc1[tid];
#pragma unroll
        for (int e = 0; e < 32; e++) acc[e] = b1;
        const float4* rep4 = (const float4*)rep;
        for (int k4 = 0; k4 < 272; k4 += 4) {
            float w0 = Wc1[(k4 + 0) * 128 + tid];
            float w1 = Wc1[(k4 + 1) * 128 + tid];
            float w2 = Wc1[(k4 + 2) * 128 + tid];
            float w3 = Wc1[(k4 + 3) * 128 + tid];
#pragma unroll
            for (int e = 0; e < 32; e++) {
                float4 r = rep4[(e * 272 + k4) >> 2];
                acc[e] = fmaf(r.x, w0, fmaf(r.y, w1, fmaf(r.z, w2, fmaf(r.w, w3, acc[e]))));
            }
        }
    }
    __syncthreads();  // all done reading rep before overwriting with o1
#pragma unroll
    for (int e = 0; e < 32; e++) o1[e * 128 + tid] = fmaxf(acc[e], 0.f);
    __syncthreads();

    // stage 2: o2[e][j] = relu(o1[e] . Wc2[:,j] + bc2[j]),  j = tid < 64
    if (tid < 64) {
        float b2 = bc2[tid];
        float acc2[32];
#pragma unroll
        for (int e = 0; e < 32; e++) acc2[e] = b2;
        const float4* o14 = (const float4*)o1;
        for (int k4 = 0; k4 < 128; k4 += 4) {
            float w0 = Wc2[(k4 + 0) * 64 + tid];
            float w1 = Wc2[(k4 + 1) * 64 + tid];
            float w2 = Wc2[(k4 + 2) * 64 + tid];
            float w3 = Wc2[(k4 + 3) * 64 + tid];
#pragma unroll
            for (int e = 0; e < 32; e++) {
                float4 r = o14[(e * 128 + k4) >> 2];
                acc2[e] = fmaf(r.x, w0, fmaf(r.y, w1, fmaf(r.z, w2, fmaf(r.w, w3, acc2[e]))));
            }
        }
#pragma unroll
        for (int e = 0; e < 32; e++) o2[e * 65 + tid] = fmaxf(acc2[e], 0.f);
    }
    __syncthreads();

    // stage 3: out[e] = o2[e] . Wc3 + bc3
    if (tid < 32) {
        int ge = e0 + tid;
        if (ge < E) {
            float s = bc3[0];
#pragma unroll
            for (int j = 0; j < 64; j++) s = fmaf(o2[tid * 65 + j], Wc3[j], s);
            out[ge] = s;
        }
    }
}

// ---------------- launch ----------------
extern "C" void kernel_launch(void* const* d_in, const int* in_sizes, int n_in,
                              void* d_out, int out_size) {
    const float* x   = (const float*)d_in[0];
    const int*   ei  = (const int*)d_in[1];
    const float* ea  = (const float*)d_in[2];
    const float* Wl1 = (const float*)d_in[3];
    const float* bl1 = (const float*)d_in[4];
    const float* Wr1 = (const float*)d_in[5];
    const float* br1 = (const float*)d_in[6];
    const float* We1 = (const float*)d_in[7];
    const float* att1 = (const float*)d_in[8];
    const float* bias1 = (const float*)d_in[9];
    const float* g1 = (const float*)d_in[10];
    const float* be1 = (const float*)d_in[11];
    const float* Wl2 = (const float*)d_in[12];
    const float* bl2 = (const float*)d_in[13];
    const float* Wr2 = (const float*)d_in[14];
    const float* br2 = (const float*)d_in[15];
    const float* We2 = (const float*)d_in[16];
    const float* att2 = (const float*)d_in[17];
    const float* bias2 = (const float*)d_in[18];
    const float* g2 = (const float*)d_in[19];
    const float* be2 = (const float*)d_in[20];
    const float* W_ih = (const float*)d_in[21];
    /* W_hh d_in[22] unused: h_prev == 0 */
    const float* b_ih = (const float*)d_in[23];
    const float* b_hh = (const float*)d_in[24];
    const float* Wc1 = (const float*)d_in[25];
    const float* bc1 = (const float*)d_in[26];
    const float* Wc2 = (const float*)d_in[27];
    const float* bc2 = (const float*)d_in[28];
    const float* Wc3 = (const float*)d_in[29];
    const float* bc3 = (const float*)d_in[30];
    float* out = (float*)d_out;

    const int* src = ei;
    const int* dst = ei + N_EDGES;

    float *xl, *xr, *ex, *den, *agg, *zv1, *zv2, *gi, *h, *Wt, *easum, *el1, *el2;
    cudaGetSymbolAddress((void**)&xl, g_xl);
    cudaGetSymbolAddress((void**)&xr, g_xr);
    cudaGetSymbolAddress((void**)&ex, g_ex);
    cudaGetSymbolAddress((void**)&den, g_den);
    cudaGetSymbolAddress((void**)&agg, g_agg);
    cudaGetSymbolAddress((void**)&zv1, g_zv1);
    cudaGetSymbolAddress((void**)&zv2, g_zv2);
    cudaGetSymbolAddress((void**)&gi, g_gi);
    cudaGetSymbolAddress((void**)&h, g_h);
    cudaGetSymbolAddress((void**)&Wt, g_Wt);
    cudaGetSymbolAddress((void**)&easum, g_easum);
    cudaGetSymbolAddress((void**)&el1, g_eeloop1);
    cudaGetSymbolAddress((void**)&el2, g_eeloop2);

    const int ZT = 256;
    int itemBlocks = (N_ITEMS + 7) / 8;  // warp per item, 8 warps/block

    // prologue: zeros + edge-attr mean + self-loop edge transforms
    zero_kernel<<<1, 32>>>(easum, 16);
    zero_kernel<<<(N_NODES * 2 + ZT - 1) / ZT, ZT>>>(den, N_NODES * 2);
    zero_kernel<<<(N_NODES * 256 + ZT - 1) / ZT, ZT>>>(agg, N_NODES * 256);
    ea_colsum<<<64, 256>>>(ea, easum, N_EDGES);
    compute_eeloop<<<1, 256>>>(easum, We1, el1, 256, 1.f / (float)N_EDGES);
    compute_eeloop<<<1, 128>>>(easum, We2, el2, 128, 1.f / (float)N_EDGES);

    // ---- GATv2 layer 1 (heads = 2) ----
    {
        dim3 grid(256 / 64, (N_NODES + 63) / 64);
        gemm_bias<<<grid, 256>>>(x, Wl1, bl1, xl, N_NODES, 128, 256);
        gemm_bias<<<grid, 256>>>(x, Wr1, br1, xr, N_NODES, 128, 256);
    }
    edge_score<2><<<itemBlocks, 256>>>(src, dst, ea, We1, att1, el1, xl, xr, ex, den);
    edge_aggregate<2><<<itemBlocks, 256>>>(src, dst, ex, den, xl, agg);
    node_finalize<<<(N_NODES + 7) / 8, 256>>>(agg, bias1, g1, be1, zv1, 2);

    // ---- GATv2 layer 2 (heads = 1) ----
    zero_kernel<<<(N_NODES * 2 + ZT - 1) / ZT, ZT>>>(den, N_NODES * 2);
    zero_kernel<<<(N_NODES * 128 + ZT - 1) / ZT, ZT>>>(agg, N_NODES * 128);
    {
        dim3 grid(128 / 64, (N_NODES + 63) / 64);
        gemm_bias<<<grid, 256>>>(zv1, Wl2, bl2, xl, N_NODES, 128, 128);
        gemm_bias<<<grid, 256>>>(zv1, Wr2, br2, xr, N_NODES, 128, 128);
    }
    edge_score<1><<<itemBlocks, 256>>>(src, dst, ea, We2, att2, el2, xl, xr, ex, den);
    edge_aggregate<1><<<itemBlocks, 256>>>(src, dst, ex, den, xl, agg);
    node_finalize<<<(N_NODES + 7) / 8, 256>>>(agg, bias2, g2, be2, zv2, 1);

    // ---- GRU (h_prev = 0) ----
    transpose_wih<<<(384 * 128 + 255) / 256, 256>>>(W_ih, Wt);
    {
        dim3 grid(384 / 64, (N_NODES + 63) / 64);
        gemm_bias<<<grid, 256>>>(zv2, Wt, b_ih, gi, N_NODES, 128, 384);
    }
    gru_kernel<<<(N_NODES * 128 + 255) / 256, 256>>>(gi, b_hh, h);

    // ---- edge classifier (original edges only) ----
    classifier<<<(N_EDGES + 31) / 32, 128>>>(h, src, dst, ea, Wc1, bc1, Wc2, bc2,
                                             Wc3, bc3, out, N_EDGES);
}